// round 10
// baseline (speedup 1.0000x reference)
#include <cuda_runtime.h>
#include <cuda_fp16.h>
#include <cstdint>

#define Hdim  1024
#define Bsz   64
#define Tlen  512
#define FOURH 4096
#define KEFF  2048            // all cells: [Wih (1024) | Whh (1024)], plain fp16
#define NTILE 128
#define KC    128
#define NCTAS 128

#define CSZ  ((long)FOURH * KEFF)
#define WTOT (4 * CSZ)                 // 67MB of halves

// ---------------- persistent scratch (device globals; no allocations) -------
__device__ __align__(16) __half g_W[(size_t)WTOT];
__device__ __align__(16) float  g_bias[4 * FOURH];
__device__ __align__(16) __half g_xh[(size_t)Bsz * Tlen * Hdim]; // 67MB
__device__ __align__(16) __half g_hf0[2][Bsz * Hdim];
__device__ __align__(16) __half g_hb0[2][Bsz * Hdim];
__device__ __align__(16) float  g_cb0[2][Bsz * Hdim];
__device__ __align__(16) __half g_hb1[2][Bsz * Hdim];
__device__ __align__(16) float  g_cb1[2][Bsz * Hdim];
__device__ unsigned g_bct;             // grid barrier: arrival counter
__device__ unsigned g_bgen;            // grid barrier: generation

// ---------------- prep kernels ---------------------------------------------
// cell 0=f0, 1=b0, 2=f1, 3=b1; rows n' = 4*h + gate.
// K: [0,1024) Wih (feature-reversed for cell 1 only); [1024,2048) Whh.
__global__ void prep_weights(const float* __restrict__ Wih_f, const float* __restrict__ Whh_f,
                             const float* __restrict__ Wih_b, const float* __restrict__ Whh_b) {
    long idx = (long)blockIdx.x * 256 + threadIdx.x;
    if (idx >= WTOT) return;
    int  cell = (int)(idx / CSZ);
    long rem  = idx % CSZ;
    int  np   = (int)(rem / KEFF);
    int  kk   = (int)(rem % KEFF);
    int  h = np >> 2, g = np & 3;
    int  n = g * Hdim + h;
    int  layer = cell >> 1;
    bool bwd   = cell & 1;
    const float* Wih = bwd ? Wih_b : Wih_f;
    const float* Whh = bwd ? Whh_b : Whh_f;

    float v;
    if (kk < Hdim) {
        int ksrc = (bwd && layer == 0) ? (Hdim - 1 - kk) : kk;  // feature reversal baked in
        v = Wih[((long)layer * FOURH + n) * Hdim + ksrc];
    } else {
        v = Whh[((long)layer * FOURH + n) * Hdim + (kk - Hdim)];
    }
    g_W[idx] = __float2half_rn(v);
}

__global__ void prep_x(const float* __restrict__ x) {
    long idx = (long)blockIdx.x * 256 + threadIdx.x;
    if (idx >= (long)Bsz * Tlen * Hdim) return;
    g_xh[idx] = __float2half_rn(x[idx]);
}

__global__ void prep_bias(const float* __restrict__ bih_f, const float* __restrict__ bhh_f,
                          const float* __restrict__ bih_b, const float* __restrict__ bhh_b) {
    int idx = blockIdx.x * 256 + threadIdx.x;
    if (idx >= 4 * FOURH) return;
    int cell = idx / FOURH, np = idx % FOURH;
    int h = np >> 2, g = np & 3;
    int n = g * Hdim + h;
    int layer = cell >> 1;
    bool bwd = cell & 1;
    const float* bi = bwd ? bih_b : bih_f;
    const float* bh = bwd ? bhh_b : bhh_f;
    g_bias[idx] = bi[layer * FOURH + n] + bh[layer * FOURH + n];
}

__global__ void prep_zero() {
    int idx = blockIdx.x * 256 + threadIdx.x;
    if (idx == 0) { g_bct = 0; g_bgen = 0; }            // reset grid barrier (graph replays!)
    if (idx >= Bsz * Hdim) return;
    __half z = __float2half_rn(0.f);
    g_hf0[0][idx] = z; g_hf0[1][idx] = z;
    g_hb0[0][idx] = z; g_hb0[1][idx] = z;
    g_hb1[0][idx] = z; g_hb1[1][idx] = z;
    g_cb0[0][idx] = 0.f; g_cb0[1][idx] = 0.f;
    g_cb1[0][idx] = 0.f; g_cb1[1][idx] = 0.f;
}

// ---------------- persistent step kernel ------------------------------------
// 128 CTAs co-resident; CTA = (cell = bid>>5, jt = bid&31). Loop k=0..512:
// cells 0,1 do layer-0 at t=k (k<512); cells 2,3 do layer-1 at t=k-1 (k>=1).
// Uniform KEFF=2048; KC=128 chunks (nch=16); 3-stage cp.async ring; ldmatrix.
#define ROWH 136                              // halves per padded smem row
#define ROWB 272                              // bytes per padded smem row
#define A_OFF 0                               // activations: 64 rows
#define B_OFF (64 * ROWB)                     // W tile: 128 rows
#define STAGE_BYTES (192 * ROWB)              // 52224
#define NSTAGE 3
#define GATES_OFF (NSTAGE * STAGE_BYTES)      // 156672
#define SMEM_TOTAL (GATES_OFF + 64 * 128 * 4) // 189440

__device__ __forceinline__ void cp16(uint32_t dst, const void* src) {
    asm volatile("cp.async.cg.shared.global [%0], [%1], 16;\n" :: "r"(dst), "l"(src));
}
__device__ __forceinline__ void ldsm4(uint32_t& r0, uint32_t& r1, uint32_t& r2, uint32_t& r3,
                                      uint32_t addr) {
    asm volatile("ldmatrix.sync.aligned.m8n8.x4.shared.b16 {%0,%1,%2,%3}, [%4];"
                 : "=r"(r0), "=r"(r1), "=r"(r2), "=r"(r3) : "r"(addr));
}

__device__ __forceinline__ void grid_barrier(unsigned gen_next) {
    __syncthreads();
    if (threadIdx.x == 0) {
        __threadfence();
        unsigned old = atomicAdd(&g_bct, 1);
        if (old == NCTAS - 1) {
            g_bct = 0;
            __threadfence();
            *(volatile unsigned*)&g_bgen = gen_next;
        } else {
            while (*(volatile unsigned*)&g_bgen < gen_next) { __nanosleep(64); }
        }
        __threadfence();
    }
    __syncthreads();
}

__global__ __launch_bounds__(256) void persist_kernel(float* __restrict__ out) {
    const int bid  = blockIdx.x;
    const int cell = bid >> 5;
    const int jt   = bid & 31;

    extern __shared__ __align__(1024) char smem[];
    float* gates = (float*)(smem + GATES_OFF);
    uint32_t smem_u32 = (uint32_t)__cvta_generic_to_shared(smem);

    const int tid  = threadIdx.x;
    const int warp = tid >> 5;
    const int lane = tid & 31;
    const int gid  = lane >> 2, tig = lane & 3;
    const int wM   = warp >> 2, wN = warp & 3;   // 2 x 4 warp grid over 64x128

    const int  nch = KEFF / KC;                  // 16
    const __half* Wg = g_W + (long)cell * CSZ + (long)jt * NTILE * KEFF;
    const float*  bias = g_bias + cell * FOURH + jt * NTILE;

    // ldmatrix per-lane base offsets (byte offsets within a stage)
    const uint32_t a_lane_off = (uint32_t)((wM * 32 + (lane & 15)) * ROWB + (lane >> 4) * 16);
    const uint32_t b_lane_off = (uint32_t)(B_OFF +
        (wN * 32 + (lane >> 4) * 8 + (lane & 7)) * ROWB + ((lane >> 3) & 1) * 16);

    for (int k = 0; k <= Tlen; k++) {
        const bool active = (cell < 2) ? (k < Tlen) : (k >= 1);
        if (active) {
            const int t  = (cell < 2) ? k : (k - 1);
            const int pp = t & 1, pm = pp ^ 1;

            const __half *a0base, *a1base;
            long a0stride, a1stride;
            if (cell < 2) {
                a0base = g_xh + (long)t * Hdim;  a0stride = (long)Tlen * Hdim;  // x_t
                a1base = g_hb0[pm];              a1stride = Hdim;               // h_b0(t-1)
            } else if (cell == 2) {
                a0base = g_hf0[pp];              a0stride = Hdim;               // h_f0(t)
                a1base = g_hb1[pm];              a1stride = Hdim;               // h_b1(t-1)
            } else {
                a0base = g_hb0[pp];              a0stride = Hdim;               // h_b0(t)
                a1base = g_hb1[pm];              a1stride = Hdim;               // h_b1(t-1)
            }

            float acc[2][4][4];
#pragma unroll
            for (int i = 0; i < 2; i++)
#pragma unroll
                for (int j = 0; j < 4; j++)
#pragma unroll
                    for (int q = 0; q < 4; q++) acc[i][j][q] = 0.f;

            auto load_chunk = [&](int c) {
                int s = c % NSTAGE;
                int kg = c * KC;
                // K map: kg<1024 -> a0; else a1
                const __half* ab; long astr; int koff;
                if (kg < Hdim) { ab = a0base; astr = a0stride; koff = kg; }
                else           { ab = a1base; astr = a1stride; koff = kg - Hdim; }
                uint32_t sbase = smem_u32 + (uint32_t)s * STAGE_BYTES;
#pragma unroll
                for (int it = 0; it < 4; it++) {                 // Act: 64 rows x 16 16B-chunks
                    int idx = tid + it * 256;
                    int r = idx >> 4, c8 = idx & 15;
                    const void* src = ab + (long)r * astr + koff + c8 * 8;
                    cp16(sbase + A_OFF + (uint32_t)(r * ROWB + c8 * 16), src);
                }
#pragma unroll
                for (int it = 0; it < 8; it++) {                 // W: 128 rows x 16 16B-chunks
                    int idx = tid + it * 256;
                    int r = idx >> 4, c8 = idx & 15;
                    const void* src = Wg + (long)r * KEFF + kg + c8 * 8;
                    cp16(sbase + B_OFF + (uint32_t)(r * ROWB + c8 * 16), src);
                }
                asm volatile("cp.async.commit_group;\n");
            };

            auto compute_chunk = [&](int s) {
                uint32_t sbase = smem_u32 + (uint32_t)s * STAGE_BYTES;
                uint32_t abase = sbase + a_lane_off;
                uint32_t bbase = sbase + b_lane_off;
#pragma unroll
                for (int k16 = 0; k16 < KC / 16; k16++) {
                    uint32_t ko = (uint32_t)k16 * 32;            // bytes
                    uint32_t a[2][4], b[4][2];
#pragma unroll
                    for (int i = 0; i < 2; i++)
                        ldsm4(a[i][0], a[i][1], a[i][2], a[i][3],
                              abase + (uint32_t)i * 16 * ROWB + ko);
#pragma unroll
                    for (int jp = 0; jp < 2; jp++)
                        ldsm4(b[2 * jp][0], b[2 * jp][1], b[2 * jp + 1][0], b[2 * jp + 1][1],
                              bbase + (uint32_t)jp * 16 * ROWB + ko);
#pragma unroll
                    for (int i = 0; i < 2; i++)
#pragma unroll
                        for (int j = 0; j < 4; j++) {
                            asm volatile(
                                "mma.sync.aligned.m16n8k16.row.col.f32.f16.f16.f32 "
                                "{%0,%1,%2,%3}, {%4,%5,%6,%7}, {%8,%9}, {%0,%1,%2,%3};\n"
                                : "+f"(acc[i][j][0]), "+f"(acc[i][j][1]),
                                  "+f"(acc[i][j][2]), "+f"(acc[i][j][3])
                                : "r"(a[i][0]), "r"(a[i][1]), "r"(a[i][2]), "r"(a[i][3]),
                                  "r"(b[j][0]), "r"(b[j][1]));
                        }
                }
            };

            // 3-stage pipeline: prefetch 2; always one commit per iter (tail-safe waits)
            load_chunk(0);
            load_chunk(1);
            for (int c = 0; c < nch; c++) {
                asm volatile("cp.async.wait_group 1;\n");
                __syncthreads();
                compute_chunk(c % NSTAGE);
                if (c + 2 < nch) load_chunk(c + 2);
                else             asm volatile("cp.async.commit_group;\n");
            }

            // epilogue: accum frags -> smem gates [64 batch][128 gate]
            __syncthreads();
#pragma unroll
            for (int i = 0; i < 2; i++)
#pragma unroll
                for (int j = 0; j < 4; j++) {
                    int r0 = wM * 32 + i * 16 + gid;
                    int cb = wN * 32 + j * 8 + 2 * tig;
                    gates[r0 * 128 + cb]           = acc[i][j][0];
                    gates[r0 * 128 + cb + 1]       = acc[i][j][1];
                    gates[(r0 + 8) * 128 + cb]     = acc[i][j][2];
                    gates[(r0 + 8) * 128 + cb + 1] = acc[i][j][3];
                }
            __syncthreads();

            const float* cprev = (cell < 2) ? g_cb0[pm] : g_cb1[pm];
            for (int p = tid; p < 2048; p += 256) {
                int b  = p >> 5, hl = p & 31;
                int hg = jt * 32 + hl;
                float4 gv = *(const float4*)(gates + b * 128 + 4 * hl);
                float4 bv = *(const float4*)(bias + 4 * hl);
                float ig = gv.x + bv.x;
                float fg = gv.y + bv.y;
                float gg = gv.z + bv.z;
                float og = gv.w + bv.w;
                float cp = cprev[b * Hdim + hg];
                float si = 1.f / (1.f + __expf(-ig));
                float sf = 1.f / (1.f + __expf(-fg));
                float so = 1.f / (1.f + __expf(-og));
                float cn = sf * cp + si * tanhf(gg);
                float hn = so * tanhf(cn);
                long sidx = (long)b * Hdim + hg;
                if (cell == 0) {                                  // f0: h feeds layer1
                    g_hf0[pp][sidx] = __float2half_rn(hn);
                } else if (cell == 1) {                           // b0: layer-0 carry
                    g_hb0[pp][sidx] = __float2half_rn(hn);
                    g_cb0[pp][sidx] = cn;
                } else {                                          // layer 1 -> outputs
                    int halfoff = (cell == 2) ? 0 : Hdim;
                    long oidx = ((long)b * Tlen + t) * (2 * Hdim) + halfoff + hg;
                    out[oidx] = hn;
                    out[(long)Bsz * Tlen * 2 * Hdim + oidx] = cn;
                    if (t == Tlen - 1) {
                        long lbase = 2L * Bsz * Tlen * 2 * Hdim;
                        out[lbase + (long)b * 2 * Hdim + halfoff + hg] = hn;
                        out[lbase + (long)Bsz * 2 * Hdim + (long)b * 2 * Hdim + halfoff + hg] = cn;
                    }
                    if (cell == 3) {                              // b1: layer-1 carry
                        g_hb1[pp][sidx] = __float2half_rn(hn);
                        g_cb1[pp][sidx] = cn;
                    }
                }
            }
        }
        grid_barrier((unsigned)(k + 1));
    }
}

// ---------------- launcher --------------------------------------------------
extern "C" void kernel_launch(void* const* d_in, const int* in_sizes, int n_in,
                              void* d_out, int out_size) {
    const float* x     = (const float*)d_in[0];
    const float* Wih_f = (const float*)d_in[1];
    const float* Whh_f = (const float*)d_in[2];
    const float* bih_f = (const float*)d_in[3];
    const float* bhh_f = (const float*)d_in[4];
    const float* Wih_b = (const float*)d_in[5];
    const float* Whh_b = (const float*)d_in[6];
    const float* bih_b = (const float*)d_in[7];
    const float* bhh_b = (const float*)d_in[8];
    float* out = (float*)d_out;

    cudaFuncSetAttribute(persist_kernel, cudaFuncAttributeMaxDynamicSharedMemorySize, SMEM_TOTAL);

    {
        long n = WTOT;
        prep_weights<<<(unsigned)((n + 255) / 256), 256>>>(Wih_f, Whh_f, Wih_b, Whh_b);
    }
    {
        long n = (long)Bsz * Tlen * Hdim;
        prep_x<<<(unsigned)((n + 255) / 256), 256>>>(x);
    }
    prep_bias<<<(4 * FOURH + 255) / 256, 256>>>(bih_f, bhh_f, bih_b, bhh_b);
    prep_zero<<<(Bsz * Hdim + 255) / 256, 256>>>();

    persist_kernel<<<NCTAS, 256, SMEM_TOTAL>>>(out);
}

// round 13
// speedup vs baseline: 1.5795x; 1.5795x over previous
#include <cuda_runtime.h>
#include <cuda_fp16.h>
#include <cstdint>

#define Hdim  1024
#define Bsz   64
#define Tlen  512
#define FOURH 4096
#define KEFF  2048            // all cells: [Wih (1024) | Whh (1024)], plain fp16
#define WSTRIDE 2176          // padded weight row stride (4352 B, breaks pow2 aliasing)
#define HSTR  1088            // padded activation/state row stride (2176 B)
#define NTILE 128
#define KC    128
#define NCTAS 128

#define CSZ  ((long)FOURH * WSTRIDE)
#define WTOT (4 * CSZ)                 // 71MB of halves (padded)

// ---------------- persistent scratch (device globals; no allocations) -------
__device__ __align__(16) __half g_W[(size_t)WTOT];
__device__ __align__(16) float  g_bias[4 * FOURH];
__device__ __align__(16) __half g_xh[(size_t)Tlen * Bsz * HSTR];  // [t][b][h], padded
__device__ __align__(16) __half g_hf0[2][Bsz * HSTR];
__device__ __align__(16) __half g_hb0[2][Bsz * HSTR];
__device__ __align__(16) float  g_cb0[2][Bsz * HSTR];
__device__ __align__(16) __half g_hb1[2][Bsz * HSTR];
__device__ __align__(16) float  g_cb1[2][Bsz * HSTR];
__device__ unsigned g_bct;             // grid barrier: arrival counter
__device__ unsigned g_bgen;            // grid barrier: generation

// ---------------- prep kernels ---------------------------------------------
// cell 0=f0, 1=b0, 2=f1, 3=b1; rows n' = 4*h + gate.
// K: [0,1024) Wih (feature-reversed for cell 1 only); [1024,2048) Whh; [2048,2176) pad.
__global__ void prep_weights(const float* __restrict__ Wih_f, const float* __restrict__ Whh_f,
                             const float* __restrict__ Wih_b, const float* __restrict__ Whh_b) {
    long idx = (long)blockIdx.x * 256 + threadIdx.x;
    if (idx >= WTOT) return;
    int  cell = (int)(idx / CSZ);
    long rem  = idx % CSZ;
    int  np   = (int)(rem / WSTRIDE);
    int  kk   = (int)(rem % WSTRIDE);
    if (kk >= KEFF) { g_W[idx] = __float2half_rn(0.f); return; }   // padding
    int  h = np >> 2, g = np & 3;
    int  n = g * Hdim + h;
    int  layer = cell >> 1;
    bool bwd   = cell & 1;
    const float* Wih = bwd ? Wih_b : Wih_f;
    const float* Whh = bwd ? Whh_b : Whh_f;

    float v;
    if (kk < Hdim) {
        int ksrc = (bwd && layer == 0) ? (Hdim - 1 - kk) : kk;  // feature reversal baked in
        v = Wih[((long)layer * FOURH + n) * Hdim + ksrc];
    } else {
        v = Whh[((long)layer * FOURH + n) * Hdim + (kk - Hdim)];
    }
    g_W[idx] = __float2half_rn(v);
}

// x: [B][T][H] fp32 -> g_xh [t][b*HSTR + h] fp16 (padding zeroed)
__global__ void prep_x(const float* __restrict__ x) {
    long idx = (long)blockIdx.x * 256 + threadIdx.x;
    if (idx >= (long)Tlen * Bsz * HSTR) return;
    int  h  = (int)(idx % HSTR);
    long bt = idx / HSTR;
    int  b  = (int)(bt % Bsz);
    int  t  = (int)(bt / Bsz);
    float v = (h < Hdim) ? x[((long)b * Tlen + t) * Hdim + h] : 0.f;
    g_xh[((long)t * Bsz + b) * HSTR + h] = __float2half_rn(v);
}

__global__ void prep_bias(const float* __restrict__ bih_f, const float* __restrict__ bhh_f,
                          const float* __restrict__ bih_b, const float* __restrict__ bhh_b) {
    int idx = blockIdx.x * 256 + threadIdx.x;
    if (idx >= 4 * FOURH) return;
    int cell = idx / FOURH, np = idx % FOURH;
    int h = np >> 2, g = np & 3;
    int n = g * Hdim + h;
    int layer = cell >> 1;
    bool bwd = cell & 1;
    const float* bi = bwd ? bih_b : bih_f;
    const float* bh = bwd ? bhh_b : bhh_f;
    g_bias[idx] = bi[layer * FOURH + n] + bh[layer * FOURH + n];
}

__global__ void prep_zero() {
    int idx = blockIdx.x * 256 + threadIdx.x;
    if (idx == 0) { g_bct = 0; g_bgen = 0; }            // reset grid barrier (graph replays!)
    if (idx >= Bsz * HSTR) return;
    __half z = __float2half_rn(0.f);
    g_hf0[0][idx] = z; g_hf0[1][idx] = z;
    g_hb0[0][idx] = z; g_hb0[1][idx] = z;
    g_hb1[0][idx] = z; g_hb1[1][idx] = z;
    g_cb0[0][idx] = 0.f; g_cb0[1][idx] = 0.f;
    g_cb1[0][idx] = 0.f; g_cb1[1][idx] = 0.f;
}

// ---------------- persistent step kernel ------------------------------------
// 128 CTAs co-resident; CTA = (cell = bid>>5, jt = bid&31). Loop k=0..512:
// cells 0,1 do layer-0 at t=k (k<512); cells 2,3 do layer-1 at t=k-1 (k>=1).
// KEFF=2048 (nch=16); KC=128; 3-stage cp.async ring; ldmatrix fragment loads.
#define ROWH 136                              // halves per padded smem row
#define ROWB 272                              // bytes per padded smem row
#define A_OFF 0                               // activations: 64 rows
#define B_OFF (64 * ROWB)                     // W tile: 128 rows
#define STAGE_BYTES (192 * ROWB)              // 52224
#define NSTAGE 3
#define GATES_OFF (NSTAGE * STAGE_BYTES)      // 156672
#define SMEM_TOTAL (GATES_OFF + 64 * 128 * 4) // 189440

__device__ __forceinline__ void cp16(uint32_t dst, const void* src) {
    asm volatile("cp.async.cg.shared.global [%0], [%1], 16;\n" :: "r"(dst), "l"(src));
}
__device__ __forceinline__ void ldsm4(uint32_t& r0, uint32_t& r1, uint32_t& r2, uint32_t& r3,
                                      uint32_t addr) {
    asm volatile("ldmatrix.sync.aligned.m8n8.x4.shared.b16 {%0,%1,%2,%3}, [%4];"
                 : "=r"(r0), "=r"(r1), "=r"(r2), "=r"(r3) : "r"(addr));
}

__device__ __forceinline__ void grid_barrier(unsigned gen_next) {
    __syncthreads();
    if (threadIdx.x == 0) {
        __threadfence();
        unsigned old = atomicAdd(&g_bct, 1);
        if (old == NCTAS - 1) {
            g_bct = 0;
            __threadfence();
            *(volatile unsigned*)&g_bgen = gen_next;
        } else {
            while (*(volatile unsigned*)&g_bgen < gen_next) { __nanosleep(64); }
        }
        __threadfence();
    }
    __syncthreads();
}

__global__ __launch_bounds__(256) void persist_kernel(float* __restrict__ out) {
    const int bid  = blockIdx.x;
    const int cell = bid >> 5;
    const int jt   = bid & 31;

    extern __shared__ __align__(1024) char smem[];
    float* gates = (float*)(smem + GATES_OFF);
    uint32_t smem_u32 = (uint32_t)__cvta_generic_to_shared(smem);

    const int tid  = threadIdx.x;
    const int warp = tid >> 5;
    const int lane = tid & 31;
    const int gid  = lane >> 2, tig = lane & 3;
    const int wM   = warp >> 2, wN = warp & 3;   // 2 x 4 warp grid over 64x128

    const int  nch = KEFF / KC;                  // 16
    const __half* Wg = g_W + (long)cell * CSZ + (long)jt * NTILE * WSTRIDE;
    const float*  bias = g_bias + cell * FOURH + jt * NTILE;

    // ldmatrix per-lane base offsets (byte offsets within a stage)
    const uint32_t a_lane_off = (uint32_t)((wM * 32 + (lane & 15)) * ROWB + (lane >> 4) * 16);
    const uint32_t b_lane_off = (uint32_t)(B_OFF +
        (wN * 32 + (lane >> 4) * 8 + (lane & 7)) * ROWB + ((lane >> 3) & 1) * 16);

    for (int k = 0; k <= Tlen; k++) {
        const bool active = (cell < 2) ? (k < Tlen) : (k >= 1);
        if (active) {
            const int t  = (cell < 2) ? k : (k - 1);
            const int pp = t & 1, pm = pp ^ 1;

            // A operand sources: two 1024-wide halves, all rows stride HSTR
            const __half *a0base, *a1base;
            if (cell < 2) {
                a0base = g_xh + (long)t * Bsz * HSTR;  // x_t [b][h]
                a1base = g_hb0[pm];                    // h_b0(t-1)
            } else if (cell == 2) {
                a0base = g_hf0[pp];                    // h_f0(t)
                a1base = g_hb1[pm];                    // h_b1(t-1)
            } else {
                a0base = g_hb0[pp];                    // h_b0(t)
                a1base = g_hb1[pm];                    // h_b1(t-1)
            }

            float acc[2][4][4];
#pragma unroll
            for (int i = 0; i < 2; i++)
#pragma unroll
                for (int j = 0; j < 4; j++)
#pragma unroll
                    for (int q = 0; q < 4; q++) acc[i][j][q] = 0.f;

            auto load_chunk = [&](int c) {
                int s = c % NSTAGE;
                int kg = c * KC;
                // K map: kg<1024 -> a0; else a1
                const __half* ab; int koff;
                if (kg < Hdim) { ab = a0base; koff = kg; }
                else           { ab = a1base; koff = kg - Hdim; }
                uint32_t sbase = smem_u32 + (uint32_t)s * STAGE_BYTES;
#pragma unroll
                for (int it = 0; it < 4; it++) {                 // Act: 64 rows x 16 16B-chunks
                    int idx = tid + it * 256;
                    int r = idx >> 4, c8 = idx & 15;
                    const void* src = ab + (long)r * HSTR + koff + c8 * 8;
                    cp16(sbase + A_OFF + (uint32_t)(r * ROWB + c8 * 16), src);
                }
#pragma unroll
                for (int it = 0; it < 8; it++) {                 // W: 128 rows x 16 16B-chunks
                    int idx = tid + it * 256;
                    int r = idx >> 4, c8 = idx & 15;
                    const void* src = Wg + (long)r * WSTRIDE + kg + c8 * 8;
                    cp16(sbase + B_OFF + (uint32_t)(r * ROWB + c8 * 16), src);
                }
                asm volatile("cp.async.commit_group;\n");
            };

            auto compute_chunk = [&](int s) {
                uint32_t sbase = smem_u32 + (uint32_t)s * STAGE_BYTES;
                uint32_t abase = sbase + a_lane_off;
                uint32_t bbase = sbase + b_lane_off;
#pragma unroll
                for (int k16 = 0; k16 < KC / 16; k16++) {
                    uint32_t ko = (uint32_t)k16 * 32;            // bytes
                    uint32_t a[2][4], b[4][2];
#pragma unroll
                    for (int i = 0; i < 2; i++)
                        ldsm4(a[i][0], a[i][1], a[i][2], a[i][3],
                              abase + (uint32_t)i * 16 * ROWB + ko);
#pragma unroll
                    for (int jp = 0; jp < 2; jp++)
                        ldsm4(b[2 * jp][0], b[2 * jp][1], b[2 * jp + 1][0], b[2 * jp + 1][1],
                              bbase + (uint32_t)jp * 16 * ROWB + ko);
#pragma unroll
                    for (int i = 0; i < 2; i++)
#pragma unroll
                        for (int j = 0; j < 4; j++) {
                            asm volatile(
                                "mma.sync.aligned.m16n8k16.row.col.f32.f16.f16.f32 "
                                "{%0,%1,%2,%3}, {%4,%5,%6,%7}, {%8,%9}, {%0,%1,%2,%3};\n"
                                : "+f"(acc[i][j][0]), "+f"(acc[i][j][1]),
                                  "+f"(acc[i][j][2]), "+f"(acc[i][j][3])
                                : "r"(a[i][0]), "r"(a[i][1]), "r"(a[i][2]), "r"(a[i][3]),
                                  "r"(b[j][0]), "r"(b[j][1]));
                        }
                }
            };

            // 3-stage pipeline: prefetch 2; always one commit per iter (tail-safe waits)
            load_chunk(0);
            load_chunk(1);
            for (int c = 0; c < nch; c++) {
                asm volatile("cp.async.wait_group 1;\n");
                __syncthreads();
                compute_chunk(c % NSTAGE);
                if (c + 2 < nch) load_chunk(c + 2);
                else             asm volatile("cp.async.commit_group;\n");
            }

            // epilogue: accum frags -> smem gates [64 batch][128 gate]
            __syncthreads();
#pragma unroll
            for (int i = 0; i < 2; i++)
#pragma unroll
                for (int j = 0; j < 4; j++) {
                    int r0 = wM * 32 + i * 16 + gid;
                    int cb = wN * 32 + j * 8 + 2 * tig;
                    gates[r0 * 128 + cb]           = acc[i][j][0];
                    gates[r0 * 128 + cb + 1]       = acc[i][j][1];
                    gates[(r0 + 8) * 128 + cb]     = acc[i][j][2];
                    gates[(r0 + 8) * 128 + cb + 1] = acc[i][j][3];
                }
            __syncthreads();

            const float* cprev = (cell < 2) ? g_cb0[pm] : g_cb1[pm];
            for (int p = tid; p < 2048; p += 256) {
                int b  = p >> 5, hl = p & 31;
                int hg = jt * 32 + hl;
                float4 gv = *(const float4*)(gates + b * 128 + 4 * hl);
                float4 bv = *(const float4*)(bias + 4 * hl);
                float ig = gv.x + bv.x;
                float fg = gv.y + bv.y;
                float gg = gv.z + bv.z;
                float og = gv.w + bv.w;
                float cp = cprev[b * HSTR + hg];
                float si = 1.f / (1.f + __expf(-ig));
                float sf = 1.f / (1.f + __expf(-fg));
                float so = 1.f / (1.f + __expf(-og));
                float cn = sf * cp + si * tanhf(gg);
                float hn = so * tanhf(cn);
                long sidx = (long)b * HSTR + hg;
                if (cell == 0) {                                  // f0: h feeds layer1
                    g_hf0[pp][sidx] = __float2half_rn(hn);
                } else if (cell == 1) {                           // b0: layer-0 carry
                    g_hb0[pp][sidx] = __float2half_rn(hn);
                    g_cb0[pp][sidx] = cn;
                } else {                                          // layer 1 -> outputs
                    int halfoff = (cell == 2) ? 0 : Hdim;
                    long oidx = ((long)b * Tlen + t) * (2 * Hdim) + halfoff + hg;
                    out[oidx] = hn;
                    out[(long)Bsz * Tlen * 2 * Hdim + oidx] = cn;
                    if (t == Tlen - 1) {
                        long lbase = 2L * Bsz * Tlen * 2 * Hdim;
                        out[lbase + (long)b * 2 * Hdim + halfoff + hg] = hn;
                        out[lbase + (long)Bsz * 2 * Hdim + (long)b * 2 * Hdim + halfoff + hg] = cn;
                    }
                    if (cell == 3) {                              // b1: layer-1 carry
                        g_hb1[pp][sidx] = __float2half_rn(hn);
                        g_cb1[pp][sidx] = cn;
                    }
                }
            }
        }
        grid_barrier((unsigned)(k + 1));
    }
}

// ---------------- launcher --------------------------------------------------
extern "C" void kernel_launch(void* const* d_in, const int* in_sizes, int n_in,
                              void* d_out, int out_size) {
    const float* x     = (const float*)d_in[0];
    const float* Wih_f = (const float*)d_in[1];
    const float* Whh_f = (const float*)d_in[2];
    const float* bih_f = (const float*)d_in[3];
    const float* bhh_f = (const float*)d_in[4];
    const float* Wih_b = (const float*)d_in[5];
    const float* Whh_b = (const float*)d_in[6];
    const float* bih_b = (const float*)d_in[7];
    const float* bhh_b = (const float*)d_in[8];
    float* out = (float*)d_out;

    cudaFuncSetAttribute(persist_kernel, cudaFuncAttributeMaxDynamicSharedMemorySize, SMEM_TOTAL);

    {
        long n = WTOT;
        prep_weights<<<(unsigned)((n + 255) / 256), 256>>>(Wih_f, Whh_f, Wih_b, Whh_b);
    }
    {
        long n = (long)Tlen * Bsz * HSTR;
        prep_x<<<(unsigned)((n + 255) / 256), 256>>>(x);
    }
    prep_bias<<<(4 * FOURH + 255) / 256, 256>>>(bih_f, bhh_f, bih_b, bhh_b);
    prep_zero<<<(Bsz * HSTR + 255) / 256, 256>>>();

    persist_kernel<<<NCTAS, 256, SMEM_TOTAL>>>(out);
}